// round 8
// baseline (speedup 1.0000x reference)
#include <cuda_runtime.h>
#include <cuda_bf16.h>
#include <math.h>
#include <stdint.h>

#define EMBX 300
#define EMBP 320
#define HX 512
#define HHX 256
#define BX 128
#define LX 128
#define NX (BX*LX)          /* 16384 */
#define SX 10
#define LAYERSX 7
#define K_SAGE 1024

#define SZ_HID (NX*2*HX)
#define OFF_GE SZ_HID
#define OFF_OV (SZ_HID + 2*BX*HX)
#define HIDQ ((size_t)(NX+1)*HX)

// ---------------- scratch (device globals) ----------------
__device__ __align__(16) __nv_bfloat16 g_embh[(size_t)NX*EMBP];
__device__ __align__(16) __nv_bfloat16 g_embl[(size_t)NX*EMBP];
__device__ __align__(16) __nv_bfloat16 g_wihh[2][(size_t)1024*EMBP];
__device__ __align__(16) __nv_bfloat16 g_wihl[2][(size_t)1024*EMBP];
__device__ __align__(16) __nv_bfloat16 g_wh[2][LAYERSX][(size_t)HX*K_SAGE];
__device__ __align__(16) __nv_bfloat16 g_wl[2][LAYERSX][(size_t)HX*K_SAGE];
__device__ __align__(16) __nv_bfloat16 g_meanh[2][(size_t)NX*HX];
__device__ __align__(16) __nv_bfloat16 g_meanl[2][(size_t)NX*HX];
__device__ __align__(16) __nv_bfloat16 g_nreph[(size_t)(NX+1)*HX];
__device__ __align__(16) __nv_bfloat16 g_nrepl[(size_t)(NX+1)*HX];
__device__ __align__(16) __nv_bfloat16 g_hidh[4][HIDQ];   /* [dir*2+pp] */
__device__ __align__(16) __nv_bfloat16 g_hidl[4][HIDQ];
__device__ __align__(16) float g_xp[2][(size_t)NX*1024];
__device__ __align__(16) float g_len[2][NX];
__device__ __align__(16) float g_bias[2][1024];
__device__ __align__(16) float g_sbias[2][LAYERSX*HX];
__device__ __align__(16) float g_whhq[2][HHX*HHX*4];

// ---------------- helpers ----------------
#define SWZ(o) ((o) ^ (((o) >> 3) & 0x70))

__device__ __forceinline__ uint32_t s2u(const void* p) {
    uint32_t a;
    asm("{ .reg .u64 t; cvta.to.shared.u64 t, %1; cvt.u32.u64 %0, t; }"
        : "=r"(a) : "l"(p));
    return a;
}
__device__ __forceinline__ void cpa16(uint32_t d, const void* g) {
    asm volatile("cp.async.cg.shared.global [%0], [%1], 16;" :: "r"(d), "l"(g));
}
__device__ __forceinline__ void ldsm4(uint32_t* r, uint32_t addr) {
    asm volatile("ldmatrix.sync.aligned.m8n8.x4.shared.b16 {%0,%1,%2,%3}, [%4];"
        : "=r"(r[0]), "=r"(r[1]), "=r"(r[2]), "=r"(r[3]) : "r"(addr));
}
__device__ __forceinline__ void mma16816(float* d, const uint32_t* a, const uint32_t* b) {
    asm volatile("mma.sync.aligned.m16n8k16.row.col.f32.bf16.bf16.f32 "
        "{%0,%1,%2,%3}, {%4,%5,%6,%7}, {%8,%9}, {%0,%1,%2,%3};"
        : "+f"(d[0]), "+f"(d[1]), "+f"(d[2]), "+f"(d[3])
        : "r"(a[0]), "r"(a[1]), "r"(a[2]), "r"(a[3]), "r"(b[0]), "r"(b[1]));
}
__device__ __forceinline__ void fma2(unsigned long long& d,
                                     unsigned long long a, unsigned long long b) {
    asm("fma.rn.f32x2 %0, %1, %2, %0;" : "+l"(d) : "l"(a), "l"(b));
}
__device__ __forceinline__ float plo(unsigned long long v) {
    return __uint_as_float((unsigned)(v & 0xffffffffu));
}
__device__ __forceinline__ float phi(unsigned long long v) {
    return __uint_as_float((unsigned)(v >> 32));
}
__device__ __forceinline__ void bsplit(float a, __nv_bfloat16& h, __nv_bfloat16& l) {
    h = __float2bfloat16(a);
    l = __float2bfloat16(a - __bfloat162float(h));
}
__device__ __forceinline__ float fsig(float x) {
    return __fdividef(1.f, 1.f + __expf(-x));
}
__device__ __forceinline__ float ftanh(float x) {
    return 2.f*fsig(2.f*x) - 1.f;
}
__device__ __forceinline__ float b2f(__nv_bfloat16 v) { return __bfloat162float(v); }

// ---------------- embedding lookup -> bf16 hi/lo, K padded to 320 ----------
__global__ void k_embed(const int* __restrict__ feat, const float* __restrict__ Wemb)
{
    int idx = blockIdx.x * blockDim.x + threadIdx.x;
    if (idx >= NX*EMBP) return;
    int n = idx / EMBP, e = idx - n*EMBP;
    float v = 0.f;
    if (e < EMBX) v = Wemb[(size_t)feat[n]*EMBX + e];
    __nv_bfloat16 h, l; bsplit(v, h, l);
    g_embh[idx] = h; g_embl[idx] = l;
}

// ---------------- bias precompute: bih+bhh, packed SAGE biases -------------
__global__ void k_bias(const float* bihf, const float* bhhf,
                       const float* bihb, const float* bhhb,
                       const float* fwb, const float* bwb)
{
    int j = blockIdx.x * blockDim.x + threadIdx.x;
    if (j < 4*HHX) {
        g_bias[0][j] = bihf[j] + bhhf[j];
        g_bias[1][j] = bihb[j] + bhhb[j];
    }
    if (j < LAYERSX*HX) {
        g_sbias[0][j] = fwb[j];
        g_sbias[1][j] = bwb[j];
    }
}

// ---------------- Wih split -> bf16 hi/lo, padded to 320 -------------------
__global__ void k_split_wih(const float* __restrict__ Wf, const float* __restrict__ Wb)
{
    int idx = blockIdx.x * blockDim.x + threadIdx.x;
    if (idx >= 2*1024*EMBP) return;
    int d = idx / (1024*EMBP);
    int rem = idx - d*(1024*EMBP);
    int r = rem / EMBP, e = rem - r*EMBP;
    const float* W = d ? Wb : Wf;
    float v = (e < EMBX) ? W[(size_t)r*EMBX + e] : 0.f;
    __nv_bfloat16 h, l; bsplit(v, h, l);
    g_wihh[d][rem] = h; g_wihl[d][rem] = l;
}

// ---------------- SAGE W split -> bf16 hi/lo -------------------------------
__global__ void k_split_sagew(const float* __restrict__ Wf, const float* __restrict__ Wb)
{
    const int per = LAYERSX*HX*K_SAGE;
    int idx = blockIdx.x * blockDim.x + threadIdx.x;
    if (idx >= 2*per) return;
    int d = idx / per, rem = idx - d*per;
    float v = (d ? Wb : Wf)[rem];
    __nv_bfloat16 h, l; bsplit(v, h, l);
    (&g_wh[0][0][0])[(size_t)d*per + rem] = h;
    (&g_wl[0][0][0])[(size_t)d*per + rem] = l;
}

// ---------------- Whh transpose into [k][j][{i,f,g,o}] float4 layout --------
__global__ void k_whhq(const float* __restrict__ Wf, const float* __restrict__ Wb)
{
    int idx = blockIdx.x * blockDim.x + threadIdx.x;
    if (idx >= 2*HHX*HHX) return;
    int d = idx / (HHX*HHX);
    int rem = idx - d*(HHX*HHX);
    int k = rem / HHX, j = rem - k*HHX;
    const float* W = d ? Wb : Wf;
    float4 v;
    v.x = W[(size_t)(0*HHX + j)*HHX + k];
    v.y = W[(size_t)(1*HHX + j)*HHX + k];
    v.z = W[(size_t)(2*HHX + j)*HHX + k];
    v.w = W[(size_t)(3*HHX + j)*HHX + k];
    *(float4*)&g_whhq[d][(size_t)rem*4] = v;
}

// ============ mma.sync bf16x3 GEMM, split-A, dual-direction ===============
// A row k<K1 from A1 (row stride K1), k>=K1 from A2 (row stride K-K1).
// Tile 128x128, BK=64 (SW128 swizzle), 3-stage cp.async pipeline.
__device__ __forceinline__ void ls4(uint32_t stb,
    const char* s0, const char* s1, int strA,
    const char* s2, const char* s3, int strB, int tid)
{
    const char* srcs[4] = { s0, s1, s2, s3 };
    int strs[4] = { strA, strA, strB, strB };
#pragma unroll
    for (int t4 = 0; t4 < 4; t4++) {
        uint32_t tb = stb + t4*16384;
        const char* src = srcs[t4];
        int st = strs[t4];
#pragma unroll
        for (int i = 0; i < 4; i++) {
            int q = tid + i*256;
            int r = q >> 3, sc = q & 7;
            cpa16(tb + SWZ(r*128 + sc*16), src + (size_t)r*st + sc*16);
        }
    }
    asm volatile("cp.async.commit_group;" ::: "memory");
}

__global__ __launch_bounds__(256, 1) void k_mma_gemm(
    const __nv_bfloat16* __restrict__ A1h, const __nv_bfloat16* __restrict__ A1l,
    int K1,
    const __nv_bfloat16* __restrict__ A2h, const __nv_bfloat16* __restrict__ A2l,
    const __nv_bfloat16* __restrict__ Bh, const __nv_bfloat16* __restrict__ Bl,
    const float* __restrict__ bias,
    float* __restrict__ Cf,
    __nv_bfloat16* __restrict__ Chh, __nv_bfloat16* __restrict__ Chl,
    int Ncols, int K, int relu, int outBf,
    size_t sA1, size_t sA2, size_t sB, size_t sBias, size_t sC)
{
    extern __shared__ char dsm[];
    const int z = blockIdx.z;
    A1h += (size_t)z*sA1;  A1l += (size_t)z*sA1;
    A2h += (size_t)z*sA2;  A2l += (size_t)z*sA2;
    Bh += (size_t)z*sB;  Bl += (size_t)z*sB;
    bias += (size_t)z*sBias;

    const int tid = threadIdx.x;
    const int wid = tid >> 5, lane = tid & 31;
    const int row0 = blockIdx.y << 7;
    const int col0 = blockIdx.x << 7;
    const int K2 = K - K1;
    const int nch = K >> 6, nchA1 = K1 >> 6;

    uint32_t sb = s2u(dsm);
    sb = (sb + 1023u) & ~1023u;

    const char* A1hb = (const char*)(A1h + (size_t)row0*K1);
    const char* A1lb = (const char*)(A1l + (size_t)row0*K1);
    const char* A2hb = (const char*)(A2h + (size_t)row0*K2);
    const char* A2lb = (const char*)(A2l + (size_t)row0*K2);
    const char* Bhb  = (const char*)(Bh + (size_t)col0*K);
    const char* Blb  = (const char*)(Bl + (size_t)col0*K);

#define LOADST(SS, KC) do { \
    int kc__ = (KC); \
    const char *ah_, *al_; int strA_; \
    if (kc__ < nchA1) { ah_ = A1hb + kc__*128; al_ = A1lb + kc__*128; strA_ = K1*2; } \
    else { ah_ = A2hb + (kc__-nchA1)*128; al_ = A2lb + (kc__-nchA1)*128; strA_ = K2*2; } \
    ls4(sb + (SS)*65536, ah_, al_, strA_, Bhb + kc__*128, Blb + kc__*128, K*2, tid); \
} while (0)

    // warp tile: 32 rows x 64 cols; 8 warps = 4x2
    const int wm = (wid >> 1) * 32;
    const int wn = (wid & 1) * 64;
    const int gq8 = lane >> 3, lr = lane & 7;
    const int a_row = wm + lr + ((gq8 & 1) << 3);
    const int a_cb  = (gq8 >> 1) << 4;
    const int b_row = wn + lr + ((gq8 >> 1) << 3);
    const int b_cb  = (gq8 & 1) << 4;

    float acc[2][8][4];
#pragma unroll
    for (int mt = 0; mt < 2; mt++)
#pragma unroll
        for (int nt = 0; nt < 8; nt++)
#pragma unroll
            for (int j = 0; j < 4; j++) acc[mt][nt][j] = 0.f;

    LOADST(0, 0);
    if (nch > 1) LOADST(1, 1);

    int sidx = 0;
    for (int kc = 0; kc < nch; kc++) {
        if (kc + 1 < nch)
            asm volatile("cp.async.wait_group 1;" ::: "memory");
        else
            asm volatile("cp.async.wait_group 0;" ::: "memory");
        __syncthreads();
        if (kc + 2 < nch) {
            int ls = sidx + 2; if (ls >= 3) ls -= 3;
            LOADST(ls, kc + 2);
        }
        const uint32_t stb = sb + sidx*65536;
#pragma unroll
        for (int ks = 0; ks < 4; ks++) {
            const int k0b = ks * 32;
            uint32_t ah[2][4], al[2][4];
#pragma unroll
            for (int mt = 0; mt < 2; mt++) {
                uint32_t off = SWZ((uint32_t)((a_row + mt*16)*128 + (a_cb + k0b)));
                ldsm4(ah[mt], stb + off);
                ldsm4(al[mt], stb + 16384 + off);
            }
            uint32_t bh[4][4], bl[4][4];
#pragma unroll
            for (int gg = 0; gg < 4; gg++) {
                uint32_t off = SWZ((uint32_t)((b_row + gg*16)*128 + (b_cb + k0b)));
                ldsm4(bh[gg], stb + 32768 + off);
                ldsm4(bl[gg], stb + 49152 + off);
            }
#pragma unroll
            for (int mt = 0; mt < 2; mt++)
#pragma unroll
                for (int nt = 0; nt < 8; nt++) {
                    const uint32_t* bhp = &bh[nt >> 1][(nt & 1) * 2];
                    const uint32_t* blp = &bl[nt >> 1][(nt & 1) * 2];
                    mma16816(acc[mt][nt], ah[mt], bhp);
                    mma16816(acc[mt][nt], ah[mt], blp);
                    mma16816(acc[mt][nt], al[mt], bhp);
                }
        }
        sidx++; if (sidx >= 3) sidx = 0;
    }
#undef LOADST

    // epilogue
    const int erow = row0 + wm + (lane >> 2);
    const int ecol = col0 + wn + 2*(lane & 3);
    if (outBf) {
        Chh += (size_t)z*sC; Chl += (size_t)z*sC;
#pragma unroll
        for (int mt = 0; mt < 2; mt++)
#pragma unroll
            for (int nt = 0; nt < 8; nt++) {
                int r = erow + mt*16;
                int cc = ecol + nt*8;
                float v0 = acc[mt][nt][0] + bias[cc];
                float v1 = acc[mt][nt][1] + bias[cc+1];
                float v2 = acc[mt][nt][2] + bias[cc];
                float v3 = acc[mt][nt][3] + bias[cc+1];
                if (relu) {
                    v0 = fmaxf(v0, 0.f); v1 = fmaxf(v1, 0.f);
                    v2 = fmaxf(v2, 0.f); v3 = fmaxf(v3, 0.f);
                }
                __nv_bfloat16 h0,l0,h1,l1;
                bsplit(v0,h0,l0); bsplit(v1,h1,l1);
                *(__nv_bfloat162*)&Chh[(size_t)r*Ncols + cc] = __halves2bfloat162(h0,h1);
                *(__nv_bfloat162*)&Chl[(size_t)r*Ncols + cc] = __halves2bfloat162(l0,l1);
                bsplit(v2,h0,l0); bsplit(v3,h1,l1);
                *(__nv_bfloat162*)&Chh[(size_t)(r+8)*Ncols + cc] = __halves2bfloat162(h0,h1);
                *(__nv_bfloat162*)&Chl[(size_t)(r+8)*Ncols + cc] = __halves2bfloat162(l0,l1);
            }
    } else {
        Cf += (size_t)z*sC;
#pragma unroll
        for (int mt = 0; mt < 2; mt++)
#pragma unroll
            for (int nt = 0; nt < 8; nt++) {
                int r = erow + mt*16;
                int cc = ecol + nt*8;
                float2 v0, v1;
                v0.x = acc[mt][nt][0] + bias[cc];
                v0.y = acc[mt][nt][1] + bias[cc+1];
                v1.x = acc[mt][nt][2] + bias[cc];
                v1.y = acc[mt][nt][3] + bias[cc+1];
                if (relu) {
                    v0.x = fmaxf(v0.x, 0.f); v0.y = fmaxf(v0.y, 0.f);
                    v1.x = fmaxf(v1.x, 0.f); v1.y = fmaxf(v1.y, 0.f);
                }
                *(float2*)&Cf[(size_t)r*Ncols + cc]     = v0;
                *(float2*)&Cf[(size_t)(r+8)*Ncols + cc] = v1;
            }
    }
}

// ---------------- persistent BiLSTM (f32x2 packed gates) -------------------
__global__ __launch_bounds__(256) void k_lstm()
{
    const int dir = blockIdx.x >> 5;
    const int rg  = blockIdx.x & 31;
    const int j = threadIdx.x;
    const float* __restrict__ Wq = g_whhq[dir];
    const float* __restrict__ xp = g_xp[dir];
    __shared__ __align__(16) float2 hbuf[2][HHX][4];  // [pp][k][row] = (h,h)
#pragma unroll
    for (int r = 0; r < 4; r++) hbuf[0][j][r] = make_float2(0.f, 0.f);
    float c[4] = {0.f, 0.f, 0.f, 0.f};
    __syncthreads();
    int p = 0;
    for (int t = 0; t < LX; t++) {
        const int tseq = dir ? (LX - 1 - t) : t;
        unsigned long long aif[4] = {0ull,0ull,0ull,0ull};
        unsigned long long ago[4] = {0ull,0ull,0ull,0ull};
#pragma unroll 4
        for (int k = 0; k < HHX; k++) {
            ulonglong2 w2 = *(const ulonglong2*)&Wq[((size_t)k*HHX + j)*4];
            ulonglong2 hA = *(const ulonglong2*)&hbuf[p][k][0];
            ulonglong2 hB = *(const ulonglong2*)&hbuf[p][k][2];
            fma2(aif[0], w2.x, hA.x); fma2(ago[0], w2.y, hA.x);
            fma2(aif[1], w2.x, hA.y); fma2(ago[1], w2.y, hA.y);
            fma2(aif[2], w2.x, hB.x); fma2(ago[2], w2.y, hB.x);
            fma2(aif[3], w2.x, hB.y); fma2(ago[3], w2.y, hB.y);
        }
#pragma unroll
        for (int r = 0; r < 4; r++) {
            const int row = rg*4 + r;
            const size_t nidx = (size_t)row*LX + tseq;
            const float* xr = xp + nidx*(4*HHX);
            float gi = plo(aif[r]) + xr[j];
            float gf = phi(aif[r]) + xr[HHX + j];
            float gg = plo(ago[r]) + xr[2*HHX + j];
            float go = phi(ago[r]) + xr[3*HHX + j];
            float si = fsig(gi), sf = fsig(gf), so = fsig(go);
            float tg = ftanh(gg);
            c[r] = sf*c[r] + si*tg;
            float hv = so * ftanh(c[r]);
            hbuf[p ^ 1][j][r] = make_float2(hv, hv);
            __nv_bfloat16 hh, hl; bsplit(hv, hh, hl);
            g_nreph[nidx*HX + (size_t)dir*HHX + j] = hh;
            g_nrepl[nidx*HX + (size_t)dir*HHX + j] = hl;
        }
        __syncthreads();
        p ^= 1;
    }
}

// ---------------- padding row + zero row N of hidden buffers ----------------
__global__ void k_pad_zero(const float* __restrict__ pad)
{
    int j = threadIdx.x;
    if (j < HX) {
        __nv_bfloat16 h, l; bsplit(pad[j], h, l);
        g_nreph[(size_t)NX*HX + j] = h;
        g_nrepl[(size_t)NX*HX + j] = l;
        __nv_bfloat16 z = __float2bfloat16(0.f);
#pragma unroll
        for (int q = 0; q < 4; q++) {
            g_hidh[q][(size_t)NX*HX + j] = z;
            g_hidl[q][(size_t)NX*HX + j] = z;
        }
    }
}

// ---------------- initial hidden = node_repres[batch_nodes] ----------------
__global__ void k_init_hid(const int* __restrict__ nodes)
{
    int idx = blockIdx.x * blockDim.x + threadIdx.x;
    if (idx >= NX*HX) return;
    int n = idx >> 9, cc = idx & (HX - 1);
    size_t src = (size_t)nodes[n]*HX + cc;
    __nv_bfloat16 h = g_nreph[src], l = g_nrepl[src];
    g_hidh[0][idx] = h; g_hidl[0][idx] = l;   // dir0, pp0
    g_hidh[2][idx] = h; g_hidl[2][idx] = l;   // dir1, pp0
}

// ------- gather + mean (neighbors only) -> bf16 hi/lo; optional len --------
__global__ __launch_bounds__(128) void k_gm(
    const __nv_bfloat16* __restrict__ nh, const __nv_bfloat16* __restrict__ nl,
    size_t sN,
    const int* __restrict__ nodes,
    const int* __restrict__ adjF, const int* __restrict__ adjB,
    int computeLen)
{
    const int n = blockIdx.x;
    const int dir = blockIdx.y;
    nh += (size_t)dir*sN;  nl += (size_t)dir*sN;
    const int* adj = dir ? adjB : adjF;

    const int t = threadIdx.x;
    __shared__ int nb[SX];
    __shared__ float s_red[4][SX];
    __shared__ float s_inv;
    if (t < SX) nb[t] = adj[(size_t)nodes[n]*SX + t];
    if (!computeLen && t == 0) s_inv = 1.f / g_len[dir][n];
    __syncthreads();

    const int c = t * 4;
    float s0 = 0.f, s1 = 0.f, s2 = 0.f, s3 = 0.f;
    float rq[SX];
#pragma unroll
    for (int q = 0; q < SX; q++) {
        size_t base = (size_t)nb[q]*HX + c;
        __nv_bfloat162 h01 = *(const __nv_bfloat162*)&nh[base];
        __nv_bfloat162 h23 = *(const __nv_bfloat162*)&nh[base+2];
        __nv_bfloat162 l01 = *(const __nv_bfloat162*)&nl[base];
        __nv_bfloat162 l23 = *(const __nv_bfloat162*)&nl[base+2];
        float v0 = b2f(h01.x) + b2f(l01.x);
        float v1 = b2f(h01.y) + b2f(l01.y);
        float v2 = b2f(h23.x) + b2f(l23.x);
        float v3 = b2f(h23.y) + b2f(l23.y);
        s0 += v0; s1 += v1; s2 += v2; s3 += v3;
        if (computeLen)
            rq[q] = fmaxf(v0, 0.f) + fmaxf(v1, 0.f)
                  + fmaxf(v2, 0.f) + fmaxf(v3, 0.f);
    }
    if (computeLen) {
        const int lane = t & 31, w = t >> 5;
#pragma unroll
        for (int q = 0; q < SX; q++) {
            float x = rq[q];
#pragma unroll
            for (int o = 16; o; o >>= 1) x += __shfl_xor_sync(0xffffffffu, x, o);
            if (lane == 0) s_red[w][q] = x;
        }
        __syncthreads();
        if (t == 0) {
            float cnt = 0.f;
#pragma unroll
            for (int q = 0; q < SX; q++) {
                float tot = s_red[0][q] + s_red[1][q] + s_red[2][q] + s_red[3][q];
                if (tot > 0.f) cnt += 1.f;
            }
            g_len[dir][n] = cnt;
            s_inv = 1.f / cnt;
        }
        __syncthreads();
    }
    const float inv = s_inv;

    __nv_bfloat16 h0,l0,h1,l1,h2,l2,h3,l3;
    bsplit(s0*inv, h0, l0); bsplit(s1*inv, h1, l1);
    bsplit(s2*inv, h2, l2); bsplit(s3*inv, h3, l3);
    size_t o = (size_t)n*HX + c;
    *(__nv_bfloat162*)&g_meanh[dir][o]   = __halves2bfloat162(h0, h1);
    *(__nv_bfloat162*)&g_meanh[dir][o+2] = __halves2bfloat162(h2, h3);
    *(__nv_bfloat162*)&g_meanl[dir][o]   = __halves2bfloat162(l0, l1);
    *(__nv_bfloat162*)&g_meanl[dir][o+2] = __halves2bfloat162(l2, l3);
}

// ---------------- finalize + pool ----------------
__global__ void k_finalize(float* __restrict__ out, int fin)
{
    int idx = blockIdx.x * blockDim.x + threadIdx.x;
    if (idx >= NX*HX) return;
    int n = idx >> 9, cc = idx & (HX - 1);
    out[(size_t)n*1024 + cc] =
        b2f(g_hidh[fin][idx]) + b2f(g_hidl[fin][idx]);
    out[(size_t)n*1024 + 512 + cc] =
        b2f(g_hidh[2+fin][idx]) + b2f(g_hidl[2+fin][idx]);
    out[(size_t)OFF_OV + idx] = b2f(g_nreph[idx]) + b2f(g_nrepl[idx]);
}

__global__ void k_pool(const float* __restrict__ hid, float* __restrict__ ge)
{
    const int b = blockIdx.x;
    const int jx = threadIdx.x;
    float m = -3.402823466e38f;
    const float* base = hid + (size_t)b*LX*1024 + jx;
    for (int l = 0; l < LX; l++) m = fmaxf(m, base[(size_t)l*1024]);
    ge[(size_t)b*1024 + jx] = m;
}

// ============================ host launcher ================================
extern "C" void kernel_launch(void* const* d_in, const int* in_sizes, int n_in,
                              void* d_out, int out_size)
{
    const int*   feature_info = (const int*)d_in[0];
    const int*   batch_nodes  = (const int*)d_in[1];
    const int*   fw_adj       = (const int*)d_in[2];
    const int*   bw_adj       = (const int*)d_in[3];
    const float* W_emb        = (const float*)d_in[4];
    const float* Wih_f        = (const float*)d_in[5];
    const float* Whh_f        = (const float*)d_in[6];
    const float* bih_f        = (const float*)d_in[7];
    const float* bhh_f        = (const float*)d_in[8];
    const float* Wih_b        = (const float*)d_in[9];
    const float* Whh_b        = (const float*)d_in[10];
    const float* bih_b        = (const float*)d_in[11];
    const float* bhh_b        = (const float*)d_in[12];
    const float* padding_vec  = (const float*)d_in[13];
    const float* fw_W         = (const float*)d_in[14];
    const float* fw_b         = (const float*)d_in[15];
    const float* bw_W         = (const float*)d_in[16];
    const float* bw_b         = (const float*)d_in[17];
    float* out = (float*)d_out;

    const int DSMEM = 3*65536 + 1024;
    cudaFuncSetAttribute(k_mma_gemm, cudaFuncAttributeMaxDynamicSharedMemorySize, DSMEM);

    float *p_bias, *p_sbias, *p_xp;
    __nv_bfloat16 *p_embh, *p_embl, *p_wihh, *p_wihl, *p_wh, *p_wl;
    __nv_bfloat16 *p_meanh, *p_meanl, *p_nreph, *p_nrepl, *p_hidh, *p_hidl;
    cudaGetSymbolAddress((void**)&p_bias, g_bias);
    cudaGetSymbolAddress((void**)&p_sbias,g_sbias);
    cudaGetSymbolAddress((void**)&p_xp,   g_xp);
    cudaGetSymbolAddress((void**)&p_embh, g_embh);
    cudaGetSymbolAddress((void**)&p_embl, g_embl);
    cudaGetSymbolAddress((void**)&p_wihh, g_wihh);
    cudaGetSymbolAddress((void**)&p_wihl, g_wihl);
    cudaGetSymbolAddress((void**)&p_wh,   g_wh);
    cudaGetSymbolAddress((void**)&p_wl,   g_wl);
    cudaGetSymbolAddress((void**)&p_meanh,g_meanh);
    cudaGetSymbolAddress((void**)&p_meanl,g_meanl);
    cudaGetSymbolAddress((void**)&p_nreph,g_nreph);
    cudaGetSymbolAddress((void**)&p_nrepl,g_nrepl);
    cudaGetSymbolAddress((void**)&p_hidh, g_hidh);
    cudaGetSymbolAddress((void**)&p_hidl, g_hidl);

    // 1. embed + weight preprocessing
    k_embed<<<(NX*EMBP + 255)/256, 256>>>(feature_info, W_emb);
    k_bias<<<(LAYERSX*HX + 255)/256, 256>>>(bih_f, bhh_f, bih_b, bhh_b, fw_b, bw_b);
    k_split_wih<<<(2*1024*EMBP + 255)/256, 256>>>(Wih_f, Wih_b);
    k_split_sagew<<<(2*LAYERSX*HX*K_SAGE + 255)/256, 256>>>(fw_W, bw_W);
    k_whhq<<<(2*HHX*HHX + 255)/256, 256>>>(Whh_f, Whh_b);

    // 2. input projections (bf16x3, fp32 out), both dirs
    dim3 gxp(1024/128, NX/128, 2);
    k_mma_gemm<<<gxp, 256, DSMEM>>>(
        p_embh, p_embl, EMBP, p_embh, p_embl,
        p_wihh, p_wihl, p_bias,
        p_xp, (__nv_bfloat16*)0, (__nv_bfloat16*)0,
        1024, EMBP, 0, 0,
        0, 0, (size_t)1024*EMBP, 1024, (size_t)NX*1024);

    // 3. persistent BiLSTM -> g_nreph/l rows 0..N-1
    k_lstm<<<64, 256>>>();

    // 4. padding row / zero rows / init hidden
    k_pad_zero<<<1, 512>>>(padding_vec);
    k_init_hid<<<(NX*HX + 255)/256, 256>>>(batch_nodes);

    // 5. 7 SAGE layers; k_gm computes mean-only; GEMM A = [hid | mean]
    int pin = 0;
    dim3 ggm(NX, 2);
    dim3 gsage(HX/128, NX/128, 2);
    for (int l = 0; l < LAYERSX; l++) {
        if (l == 0)
            k_gm<<<ggm, 128>>>(p_nreph, p_nrepl, 0,
                               batch_nodes, fw_adj, bw_adj, 1);
        else
            k_gm<<<ggm, 128>>>(p_hidh + (size_t)pin*HIDQ, p_hidl + (size_t)pin*HIDQ,
                               2*HIDQ, batch_nodes, fw_adj, bw_adj, 0);
        k_mma_gemm<<<gsage, 256, DSMEM>>>(
            p_hidh + (size_t)pin*HIDQ, p_hidl + (size_t)pin*HIDQ, HX,
            p_meanh, p_meanl,
            p_wh + (size_t)l*HX*K_SAGE, p_wl + (size_t)l*HX*K_SAGE,
            p_sbias + (size_t)l*HX,
            (float*)0,
            p_hidh + (size_t)(pin^1)*HIDQ, p_hidl + (size_t)(pin^1)*HIDQ,
            HX, K_SAGE, 1, 1,
            2*HIDQ, (size_t)NX*HX, (size_t)LAYERSX*HX*K_SAGE,
            (size_t)LAYERSX*HX, 2*HIDQ);
        pin ^= 1;
    }

    // 6. outputs
    k_finalize<<<(NX*HX + 255)/256, 256>>>(out, pin);
    k_pool<<<BX, 1024>>>(out, out + OFF_GE);
    (void)in_sizes; (void)n_in; (void)out_size;
}

// round 9
// speedup vs baseline: 1.8674x; 1.8674x over previous
#include <cuda_runtime.h>
#include <cuda_bf16.h>
#include <math.h>
#include <stdint.h>

#define EMBX 300
#define EMBP 320
#define HX 512
#define HHX 256
#define BX 128
#define LX 128
#define NX (BX*LX)          /* 16384 */
#define SX 10
#define LAYERSX 7
#define K_SAGE 1024

#define SZ_HID (NX*2*HX)
#define OFF_GE SZ_HID
#define OFF_OV (SZ_HID + 2*BX*HX)

// ---------------- scratch (device globals) ----------------
__device__ __align__(16) __nv_bfloat16 g_embh[(size_t)NX*EMBP];
__device__ __align__(16) __nv_bfloat16 g_embl[(size_t)NX*EMBP];
__device__ __align__(16) __nv_bfloat16 g_wihh[2][(size_t)1024*EMBP];
__device__ __align__(16) __nv_bfloat16 g_wihl[2][(size_t)1024*EMBP];
__device__ __align__(16) __nv_bfloat16 g_wh[2][LAYERSX][(size_t)HX*K_SAGE];
__device__ __align__(16) __nv_bfloat16 g_wl[2][LAYERSX][(size_t)HX*K_SAGE];
__device__ __align__(16) __nv_bfloat16 g_cath[2][(size_t)NX*K_SAGE];
__device__ __align__(16) __nv_bfloat16 g_catl[2][(size_t)NX*K_SAGE];
__device__ __align__(16) float g_xp[2][(size_t)NX*1024];
__device__ __align__(16) float g_nrep[(size_t)(NX+1)*HX];
__device__ __align__(16) float g_hid[2][2][(size_t)(NX+1)*HX];
__device__ __align__(16) float g_len[2][NX];
__device__ __align__(16) float g_bias[2][1024];
__device__ __align__(16) float g_sbias[2][LAYERSX*HX];
__device__ __align__(16) float g_whhq[2][HHX*HHX*4];

// ---------------- helpers ----------------
#define SWZ(o) ((o) ^ (((o) >> 3) & 0x70))

__device__ __forceinline__ uint32_t s2u(const void* p) {
    uint32_t a;
    asm("{ .reg .u64 t; cvta.to.shared.u64 t, %1; cvt.u32.u64 %0, t; }"
        : "=r"(a) : "l"(p));
    return a;
}
__device__ __forceinline__ void cpa16(uint32_t d, const void* g) {
    asm volatile("cp.async.cg.shared.global [%0], [%1], 16;" :: "r"(d), "l"(g));
}
__device__ __forceinline__ void ldsm4(uint32_t* r, uint32_t addr) {
    asm volatile("ldmatrix.sync.aligned.m8n8.x4.shared.b16 {%0,%1,%2,%3}, [%4];"
        : "=r"(r[0]), "=r"(r[1]), "=r"(r[2]), "=r"(r[3]) : "r"(addr));
}
__device__ __forceinline__ void mma16816(float* d, const uint32_t* a, const uint32_t* b) {
    asm volatile("mma.sync.aligned.m16n8k16.row.col.f32.bf16.bf16.f32 "
        "{%0,%1,%2,%3}, {%4,%5,%6,%7}, {%8,%9}, {%0,%1,%2,%3};"
        : "+f"(d[0]), "+f"(d[1]), "+f"(d[2]), "+f"(d[3])
        : "r"(a[0]), "r"(a[1]), "r"(a[2]), "r"(a[3]), "r"(b[0]), "r"(b[1]));
}
__device__ __forceinline__ void bsplit(float a, __nv_bfloat16& h, __nv_bfloat16& l) {
    h = __float2bfloat16(a);
    l = __float2bfloat16(a - __bfloat162float(h));
}
__device__ __forceinline__ float fsig(float x) {
    return __fdividef(1.f, 1.f + __expf(-x));
}
__device__ __forceinline__ float ftanh(float x) {
    float e = __expf(-2.f*x);
    return __fdividef(1.f - e, 1.f + e);
}

// ---------------- embedding lookup -> bf16 hi/lo, K padded to 320 ----------
__global__ void k_embed(const int* __restrict__ feat, const float* __restrict__ Wemb)
{
    int idx = blockIdx.x * blockDim.x + threadIdx.x;
    if (idx >= NX*EMBP) return;
    int n = idx / EMBP, e = idx - n*EMBP;
    float v = 0.f;
    if (e < EMBX) v = Wemb[(size_t)feat[n]*EMBX + e];
    __nv_bfloat16 h, l; bsplit(v, h, l);
    g_embh[idx] = h; g_embl[idx] = l;
}

// ---------------- bias precompute: bih+bhh, packed SAGE biases -------------
__global__ void k_bias(const float* bihf, const float* bhhf,
                       const float* bihb, const float* bhhb,
                       const float* fwb, const float* bwb)
{
    int j = blockIdx.x * blockDim.x + threadIdx.x;
    if (j < 4*HHX) {
        g_bias[0][j] = bihf[j] + bhhf[j];
        g_bias[1][j] = bihb[j] + bhhb[j];
    }
    if (j < LAYERSX*HX) {
        g_sbias[0][j] = fwb[j];
        g_sbias[1][j] = bwb[j];
    }
}

// ---------------- Wih split -> bf16 hi/lo, padded to 320 -------------------
__global__ void k_split_wih(const float* __restrict__ Wf, const float* __restrict__ Wb)
{
    int idx = blockIdx.x * blockDim.x + threadIdx.x;
    if (idx >= 2*1024*EMBP) return;
    int d = idx / (1024*EMBP);
    int rem = idx - d*(1024*EMBP);
    int r = rem / EMBP, e = rem - r*EMBP;
    const float* W = d ? Wb : Wf;
    float v = (e < EMBX) ? W[(size_t)r*EMBX + e] : 0.f;
    __nv_bfloat16 h, l; bsplit(v, h, l);
    g_wihh[d][rem] = h; g_wihl[d][rem] = l;
}

// ---------------- SAGE W split -> bf16 hi/lo -------------------------------
__global__ void k_split_sagew(const float* __restrict__ Wf, const float* __restrict__ Wb)
{
    const int per = LAYERSX*HX*K_SAGE;
    int idx = blockIdx.x * blockDim.x + threadIdx.x;
    if (idx >= 2*per) return;
    int d = idx / per, rem = idx - d*per;
    float v = (d ? Wb : Wf)[rem];
    __nv_bfloat16 h, l; bsplit(v, h, l);
    (&g_wh[0][0][0])[(size_t)d*per + rem] = h;
    (&g_wl[0][0][0])[(size_t)d*per + rem] = l;
}

// ---------------- Whh transpose into [k][j][{i,f,g,o}] float4 layout --------
__global__ void k_whhq(const float* __restrict__ Wf, const float* __restrict__ Wb)
{
    int idx = blockIdx.x * blockDim.x + threadIdx.x;
    if (idx >= 2*HHX*HHX) return;
    int d = idx / (HHX*HHX);
    int rem = idx - d*(HHX*HHX);
    int k = rem / HHX, j = rem - k*HHX;
    const float* W = d ? Wb : Wf;
    float4 v;
    v.x = W[(size_t)(0*HHX + j)*HHX + k];
    v.y = W[(size_t)(1*HHX + j)*HHX + k];
    v.z = W[(size_t)(2*HHX + j)*HHX + k];
    v.w = W[(size_t)(3*HHX + j)*HHX + k];
    *(float4*)&g_whhq[d][(size_t)rem*4] = v;
}

// ============ mma.sync bf16x3 GEMM, dual-direction via blockIdx.z ==========
__device__ __forceinline__ void load_stage(
    uint32_t sb, int s, int kc,
    const char* A0, const char* A1, const char* B0, const char* B1,
    int K, int tid)
{
    const char* srcs[4] = { A0, A1, B0, B1 };
    uint32_t stb = sb + s*65536;
#pragma unroll
    for (int t4 = 0; t4 < 4; t4++) {
        const char* src = srcs[t4] + (size_t)kc*128;
        uint32_t tb = stb + t4*16384;
#pragma unroll
        for (int i = 0; i < 4; i++) {
            int q = tid + i*256;
            int r = q >> 3, sc = q & 7;
            cpa16(tb + SWZ(r*128 + sc*16), src + (size_t)r*(size_t)K*2 + sc*16);
        }
    }
    asm volatile("cp.async.commit_group;" ::: "memory");
}

__global__ __launch_bounds__(256, 1) void k_mma_gemm(
    const __nv_bfloat16* __restrict__ Ah, const __nv_bfloat16* __restrict__ Al,
    const __nv_bfloat16* __restrict__ Bh, const __nv_bfloat16* __restrict__ Bl,
    const float* __restrict__ bias, float* __restrict__ C,
    int Ncols, int K, int relu,
    size_t sA, size_t sB, size_t sBias, size_t sC)
{
    extern __shared__ char dsm[];
    const int z = blockIdx.z;
    Ah += (size_t)z*sA;  Al += (size_t)z*sA;
    Bh += (size_t)z*sB;  Bl += (size_t)z*sB;
    bias += (size_t)z*sBias;
    C  += (size_t)z*sC;

    const int tid = threadIdx.x;
    const int wid = tid >> 5, lane = tid & 31;
    const int row0 = blockIdx.y << 7;
    const int col0 = blockIdx.x << 7;
    const int nch = K >> 6;

    uint32_t sb = s2u(dsm);
    sb = (sb + 1023u) & ~1023u;

    const char* A0 = (const char*)(Ah + (size_t)row0*K);
    const char* A1 = (const char*)(Al + (size_t)row0*K);
    const char* B0 = (const char*)(Bh + (size_t)col0*K);
    const char* B1 = (const char*)(Bl + (size_t)col0*K);

    const int wm = (wid >> 1) * 32;
    const int wn = (wid & 1) * 64;
    const int gq8 = lane >> 3, lr = lane & 7;
    const int a_row = wm + lr + ((gq8 & 1) << 3);
    const int a_cb  = (gq8 >> 1) << 4;
    const int b_row = wn + lr + ((gq8 >> 1) << 3);
    const int b_cb  = (gq8 & 1) << 4;

    float acc[2][8][4];
#pragma unroll
    for (int mt = 0; mt < 2; mt++)
#pragma unroll
        for (int nt = 0; nt < 8; nt++)
#pragma unroll
            for (int j = 0; j < 4; j++) acc[mt][nt][j] = 0.f;

    load_stage(sb, 0, 0, A0, A1, B0, B1, K, tid);
    if (nch > 1) load_stage(sb, 1, 1, A0, A1, B0, B1, K, tid);

    int sidx = 0;
    for (int kc = 0; kc < nch; kc++) {
        if (kc + 1 < nch)
            asm volatile("cp.async.wait_group 1;" ::: "memory");
        else
            asm volatile("cp.async.wait_group 0;" ::: "memory");
        __syncthreads();
        if (kc + 2 < nch) {
            int ls = sidx + 2; if (ls >= 3) ls -= 3;
            load_stage(sb, ls, kc + 2, A0, A1, B0, B1, K, tid);
        }
        const uint32_t stb = sb + sidx*65536;
#pragma unroll
        for (int ks = 0; ks < 4; ks++) {
            const int k0b = ks * 32;
            uint32_t ah[2][4], al[2][4];
#pragma unroll
            for (int mt = 0; mt < 2; mt++) {
                uint32_t off = SWZ((uint32_t)((a_row + mt*16)*128 + (a_cb + k0b)));
                ldsm4(ah[mt], stb + off);
                ldsm4(al[mt], stb + 16384 + off);
            }
            uint32_t bh[4][4], bl[4][4];
#pragma unroll
            for (int gg = 0; gg < 4; gg++) {
                uint32_t off = SWZ((uint32_t)((b_row + gg*16)*128 + (b_cb + k0b)));
                ldsm4(bh[gg], stb + 32768 + off);
                ldsm4(bl[gg], stb + 49152 + off);
            }
#pragma unroll
            for (int mt = 0; mt < 2; mt++)
#pragma unroll
                for (int nt = 0; nt < 8; nt++) {
                    const uint32_t* bhp = &bh[nt >> 1][(nt & 1) * 2];
                    const uint32_t* blp = &bl[nt >> 1][(nt & 1) * 2];
                    mma16816(acc[mt][nt], ah[mt], bhp);
                    mma16816(acc[mt][nt], ah[mt], blp);
                    mma16816(acc[mt][nt], al[mt], bhp);
                }
        }
        sidx++; if (sidx >= 3) sidx = 0;
    }

    const int erow = row0 + wm + (lane >> 2);
    const int ecol = col0 + wn + 2*(lane & 3);
#pragma unroll
    for (int mt = 0; mt < 2; mt++)
#pragma unroll
        for (int nt = 0; nt < 8; nt++) {
            int r = erow + mt*16;
            int cc = ecol + nt*8;
            float2 v0, v1;
            v0.x = acc[mt][nt][0] + bias[cc];
            v0.y = acc[mt][nt][1] + bias[cc+1];
            v1.x = acc[mt][nt][2] + bias[cc];
            v1.y = acc[mt][nt][3] + bias[cc+1];
            if (relu) {
                v0.x = fmaxf(v0.x, 0.f); v0.y = fmaxf(v0.y, 0.f);
                v1.x = fmaxf(v1.x, 0.f); v1.y = fmaxf(v1.y, 0.f);
            }
            *(float2*)&C[(size_t)r*Ncols + cc]     = v0;
            *(float2*)&C[(size_t)(r+8)*Ncols + cc] = v1;
        }
}

// ---------------- persistent BiLSTM (scalar FFMA, fast gates) --------------
__global__ __launch_bounds__(256) void k_lstm()
{
    const int dir = blockIdx.x >> 5;
    const int rg  = blockIdx.x & 31;
    const int j = threadIdx.x;
    const float* __restrict__ Wq = g_whhq[dir];
    const float* __restrict__ xp = g_xp[dir];
    __shared__ float hbuf[2][4][HHX];
#pragma unroll
    for (int r = 0; r < 4; r++) hbuf[0][r][j] = 0.f;
    float c[4] = {0.f, 0.f, 0.f, 0.f};
    __syncthreads();
    int p = 0;
    for (int t = 0; t < LX; t++) {
        const int tseq = dir ? (LX - 1 - t) : t;
        float a0[4] = {0,0,0,0}, a1[4] = {0,0,0,0};
        float a2[4] = {0,0,0,0}, a3[4] = {0,0,0,0};
#pragma unroll 4
        for (int k = 0; k < HHX; k++) {
            float4 w = *(const float4*)&Wq[((size_t)k*HHX + j)*4];
#pragma unroll
            for (int r = 0; r < 4; r++) {
                float hv = hbuf[p][r][k];
                a0[r] = fmaf(w.x, hv, a0[r]);
                a1[r] = fmaf(w.y, hv, a1[r]);
                a2[r] = fmaf(w.z, hv, a2[r]);
                a3[r] = fmaf(w.w, hv, a3[r]);
            }
        }
#pragma unroll
        for (int r = 0; r < 4; r++) {
            const int row = rg*4 + r;
            const size_t nidx = (size_t)row*LX + tseq;
            const float* xr = xp + nidx*(4*HHX);
            float gi = a0[r] + xr[j];
            float gf = a1[r] + xr[HHX + j];
            float gg = a2[r] + xr[2*HHX + j];
            float go = a3[r] + xr[3*HHX + j];
            float si = fsig(gi), sf = fsig(gf), so = fsig(go);
            float tg = ftanh(gg);
            c[r] = sf*c[r] + si*tg;
            float hv = so * ftanh(c[r]);
            hbuf[p ^ 1][r][j] = hv;
            g_nrep[nidx*HX + (size_t)dir*HHX + j] = hv;
        }
        __syncthreads();
        p ^= 1;
    }
}

// ---------------- padding row + zero row N of hidden buffers ----------------
__global__ void k_pad_zero(const float* __restrict__ pad)
{
    int j = threadIdx.x;
    if (j < HX) {
        g_nrep[(size_t)NX*HX + j] = pad[j];
        g_hid[0][0][(size_t)NX*HX + j] = 0.f;
        g_hid[0][1][(size_t)NX*HX + j] = 0.f;
        g_hid[1][0][(size_t)NX*HX + j] = 0.f;
        g_hid[1][1][(size_t)NX*HX + j] = 0.f;
    }
}

// ---------------- initial hidden = node_repres[batch_nodes] ----------------
__global__ void k_init_hid(const int* __restrict__ nodes)
{
    int idx = blockIdx.x * blockDim.x + threadIdx.x;
    if (idx >= NX*HX) return;
    int n = idx >> 9, cc = idx & (HX - 1);
    float v = g_nrep[(size_t)nodes[n]*HX + cc];
    g_hid[0][0][idx] = v;
    g_hid[1][0][idx] = v;
}

// ------- gather + mean + concat -> bf16 hi/lo cat; optional len compute ----
__global__ __launch_bounds__(128) void k_gm(
    const float* __restrict__ selfT, size_t sSelf,
    const float* __restrict__ neighT, size_t sNeigh,
    const int* __restrict__ nodes,
    const int* __restrict__ adjF, const int* __restrict__ adjB,
    int computeLen)
{
    const int n = blockIdx.x;
    const int dir = blockIdx.y;
    selfT  += (size_t)dir*sSelf;
    neighT += (size_t)dir*sNeigh;
    const int* adj = dir ? adjB : adjF;
    __nv_bfloat16* cath = g_cath[dir];
    __nv_bfloat16* catl = g_catl[dir];

    const int t = threadIdx.x;
    __shared__ int nb[SX];
    __shared__ float s_red[4][SX];
    __shared__ float s_inv;
    if (t < SX) nb[t] = adj[(size_t)nodes[n]*SX + t];
    if (!computeLen && t == 0) s_inv = 1.f / g_len[dir][n];
    __syncthreads();

    const int c = t * 4;
    float4 s = {0.f, 0.f, 0.f, 0.f};
    float rq[SX];
#pragma unroll
    for (int q = 0; q < SX; q++) {
        const float4 v = *(const float4*)&neighT[(size_t)nb[q]*HX + c];
        s.x += v.x; s.y += v.y; s.z += v.z; s.w += v.w;
        if (computeLen) {
            rq[q] = fmaxf(v.x, 0.f) + fmaxf(v.y, 0.f)
                  + fmaxf(v.z, 0.f) + fmaxf(v.w, 0.f);
        }
    }
    if (computeLen) {
        const int lane = t & 31, w = t >> 5;
#pragma unroll
        for (int q = 0; q < SX; q++) {
            float x = rq[q];
#pragma unroll
            for (int o = 16; o; o >>= 1) x += __shfl_xor_sync(0xffffffffu, x, o);
            if (lane == 0) s_red[w][q] = x;
        }
        __syncthreads();
        if (t == 0) {
            float cnt = 0.f;
#pragma unroll
            for (int q = 0; q < SX; q++) {
                float tot = s_red[0][q] + s_red[1][q] + s_red[2][q] + s_red[3][q];
                if (tot > 0.f) cnt += 1.f;
            }
            g_len[dir][n] = cnt;
            s_inv = 1.f / cnt;
        }
        __syncthreads();
    }
    const float invlen = s_inv;

    float4 sv = *(const float4*)&selfT[(size_t)n*HX + c];
    float4 m = {s.x*invlen, s.y*invlen, s.z*invlen, s.w*invlen};

    size_t o = (size_t)n*K_SAGE + c;
    __nv_bfloat16 h0,l0,h1,l1,h2,l2,h3,l3;
    bsplit(sv.x,h0,l0); bsplit(sv.y,h1,l1); bsplit(sv.z,h2,l2); bsplit(sv.w,h3,l3);
    *(__nv_bfloat162*)&cath[o]   = __halves2bfloat162(h0,h1);
    *(__nv_bfloat162*)&cath[o+2] = __halves2bfloat162(h2,h3);
    *(__nv_bfloat162*)&catl[o]   = __halves2bfloat162(l0,l1);
    *(__nv_bfloat162*)&catl[o+2] = __halves2bfloat162(l2,l3);

    bsplit(m.x,h0,l0); bsplit(m.y,h1,l1); bsplit(m.z,h2,l2); bsplit(m.w,h3,l3);
    *(__nv_bfloat162*)&cath[o+HX]   = __halves2bfloat162(h0,h1);
    *(__nv_bfloat162*)&cath[o+HX+2] = __halves2bfloat162(h2,h3);
    *(__nv_bfloat162*)&catl[o+HX]   = __halves2bfloat162(l0,l1);
    *(__nv_bfloat162*)&catl[o+HX+2] = __halves2bfloat162(l2,l3);
}

// ---------------- finalize + pool ----------------
__global__ void k_finalize(float* __restrict__ out, int fin)
{
    int idx = blockIdx.x * blockDim.x + threadIdx.x;
    if (idx >= NX*HX) return;
    int n = idx >> 9, cc = idx & (HX - 1);
    out[(size_t)n*1024 + cc]       = g_hid[0][fin][idx];
    out[(size_t)n*1024 + 512 + cc] = g_hid[1][fin][idx];
    out[(size_t)OFF_OV + idx]      = g_nrep[idx];
}

__global__ void k_pool(const float* __restrict__ hid, float* __restrict__ ge)
{
    const int b = blockIdx.x;
    const int jx = threadIdx.x;
    float m = -3.402823466e38f;
    const float* base = hid + (size_t)b*LX*1024 + jx;
    for (int l = 0; l < LX; l++) m = fmaxf(m, base[(size_t)l*1024]);
    ge[(size_t)b*1024 + jx] = m;
}

// ============================ host launcher ================================
extern "C" void kernel_launch(void* const* d_in, const int* in_sizes, int n_in,
                              void* d_out, int out_size)
{
    const int*   feature_info = (const int*)d_in[0];
    const int*   batch_nodes  = (const int*)d_in[1];
    const int*   fw_adj       = (const int*)d_in[2];
    const int*   bw_adj       = (const int*)d_in[3];
    const float* W_emb        = (const float*)d_in[4];
    const float* Wih_f        = (const float*)d_in[5];
    const float* Whh_f        = (const float*)d_in[6];
    const float* bih_f        = (const float*)d_in[7];
    const float* bhh_f        = (const float*)d_in[8];
    const float* Wih_b        = (const float*)d_in[9];
    const float* Whh_b        = (const float*)d_in[10];
    const float* bih_b        = (const float*)d_in[11];
    const float* bhh_b        = (const float*)d_in[12];
    const float* padding_vec  = (const float*)d_in[13];
    const float* fw_W         = (const float*)d_in[14];
    const float* fw_b         = (const float*)d_in[15];
    const float* bw_W         = (const float*)d_in[16];
    const float* bw_b         = (const float*)d_in[17];
    float* out = (float*)d_out;

    const int DSMEM = 3*65536 + 1024;
    cudaFuncSetAttribute(k_mma_gemm, cudaFuncAttributeMaxDynamicSharedMemorySize, DSMEM);

    float *p_nrep, *p_hid, *p_bias, *p_sbias, *p_xp;
    __nv_bfloat16 *p_embh, *p_embl, *p_wihh, *p_wihl, *p_wh, *p_wl, *p_cath, *p_catl;
    cudaGetSymbolAddress((void**)&p_nrep, g_nrep);
    cudaGetSymbolAddress((void**)&p_hid,  g_hid);
    cudaGetSymbolAddress((void**)&p_bias, g_bias);
    cudaGetSymbolAddress((void**)&p_sbias,g_sbias);
    cudaGetSymbolAddress((void**)&p_xp,   g_xp);
    cudaGetSymbolAddress((void**)&p_embh, g_embh);
    cudaGetSymbolAddress((void**)&p_embl, g_embl);
    cudaGetSymbolAddress((void**)&p_wihh, g_wihh);
    cudaGetSymbolAddress((void**)&p_wihl, g_wihl);
    cudaGetSymbolAddress((void**)&p_wh,   g_wh);
    cudaGetSymbolAddress((void**)&p_wl,   g_wl);
    cudaGetSymbolAddress((void**)&p_cath, g_cath);
    cudaGetSymbolAddress((void**)&p_catl, g_catl);

    const size_t HIDQ = (size_t)(NX+1)*HX;
    const size_t HIDD = 2*HIDQ;
    float* hid_d[2][2];
    for (int d = 0; d < 2; d++)
        for (int q = 0; q < 2; q++)
            hid_d[d][q] = p_hid + ((size_t)d*2 + q)*HIDQ;

    // 1. embed + weight preprocessing
    k_embed<<<(NX*EMBP + 255)/256, 256>>>(feature_info, W_emb);
    k_bias<<<(LAYERSX*HX + 255)/256, 256>>>(bih_f, bhh_f, bih_b, bhh_b, fw_b, bw_b);
    k_split_wih<<<(2*1024*EMBP + 255)/256, 256>>>(Wih_f, Wih_b);
    k_split_sagew<<<(2*LAYERSX*HX*K_SAGE + 255)/256, 256>>>(fw_W, bw_W);
    k_whhq<<<(2*HHX*HHX + 255)/256, 256>>>(Whh_f, Whh_b);

    // 2. input projections, both dirs in one launch (bf16x3 mma)
    dim3 gxp(1024/128, NX/128, 2);
    k_mma_gemm<<<gxp, 256, DSMEM>>>(p_embh, p_embl, p_wihh, p_wihl,
                                    p_bias, p_xp, 1024, EMBP, 0,
                                    0, (size_t)1024*EMBP, 1024, (size_t)NX*1024);

    // 3. persistent BiLSTM -> g_nrep rows 0..N-1
    k_lstm<<<64, 256>>>();

    // 4. padding row / zero rows / init hidden
    k_pad_zero<<<1, 512>>>(padding_vec);
    k_init_hid<<<(NX*HX + 255)/256, 256>>>(batch_nodes);

    // 5. 7 SAGE layers, both dirs per launch; layer 0 fuses len computation
    int pin = 0;
    dim3 ggm(NX, 2);
    dim3 gsage(HX/128, NX/128, 2);
    for (int l = 0; l < LAYERSX; l++) {
        if (l == 0)
            k_gm<<<ggm, 128>>>(hid_d[0][pin], HIDD, p_nrep, 0,
                               batch_nodes, fw_adj, bw_adj, 1);
        else
            k_gm<<<ggm, 128>>>(hid_d[0][pin], HIDD, hid_d[0][pin], HIDD,
                               batch_nodes, fw_adj, bw_adj, 0);
        k_mma_gemm<<<gsage, 256, DSMEM>>>(
            p_cath, p_catl,
            p_wh + (size_t)l*HX*K_SAGE, p_wl + (size_t)l*HX*K_SAGE,
            p_sbias + (size_t)l*HX, hid_d[0][1 - pin],
            HX, K_SAGE, 1,
            (size_t)NX*K_SAGE, (size_t)LAYERSX*HX*K_SAGE,
            (size_t)LAYERSX*HX, HIDD);
        pin ^= 1;
    }

    // 6. outputs
    k_finalize<<<(NX*HX + 255)/256, 256>>>(out, pin);
    k_pool<<<BX, 1024>>>(out, out + OFF_GE);
    (void)in_sizes; (void)n_in; (void)out_size;
}